// round 3
// baseline (speedup 1.0000x reference)
#include <cuda_runtime.h>

// Problem constants (match reference)
#define K_VOX 12000
#define T_PTS 35
#define F_IN  7
#define D_DIM 10
#define H_DIM 400
#define W_DIM 352
#define C_OUT_DIM 128
#define EPSVAL 1e-3f

// One resident wave: 148 SMs x 4 blocks (enforced by __launch_bounds__(256,4))
#define NBLK 592
#define ZTH  192                  // zero threads per block (warps 2..7)
#define ZT   (NBLK * ZTH)         // total zero threads

// Voxel-wise results staged here (fully overwritten each launch).
__device__ float g_vox[K_VOX * C_OUT_DIM];   // 6.1 MB

#define BAR64() asm volatile("bar.sync 1, 64;" ::: "memory")

// ---------------------------------------------------------------------------
// Fat kernel: warps 0-1 of every block compute voxels; warps 2-7 stream-zero
// the 720MB output concurrently. Single wave -> compute hides under HBM writes.
// ---------------------------------------------------------------------------
__global__ __launch_bounds__(256, 4) void fat_kernel(
    const float* __restrict__ feat,     // [K, T, F]
    const float* __restrict__ w1,       // [F, 16]
    const float* __restrict__ b1,
    const float* __restrict__ gamma1, const float* __restrict__ beta1,
    const float* __restrict__ mean1,  const float* __restrict__ var1,
    const float* __restrict__ w2,       // [32, 64]
    const float* __restrict__ b2,
    const float* __restrict__ gamma2, const float* __restrict__ beta2,
    const float* __restrict__ mean2,  const float* __restrict__ var2,
    float*       __restrict__ out,      // [1, D, H, W, 128] — zeroed here
    int n4)                             // out_size / 4
{
    const int bid = blockIdx.x;
    const int tid = threadIdx.x;

    if (tid >= 64) {
        // ---------------- Zero role (warps 2..7) ----------------
        const int zid = bid * ZTH + (tid - 64);
        float4* o4 = (float4*)out;
        const float4 z = make_float4(0.f, 0.f, 0.f, 0.f);
        for (int i = zid; i < n4; i += ZT) o4[i] = z;
        return;
    }

    // ---------------- Compute role (warps 0..1, 64 threads) ----------------
    const int v = tid;   // output channel (owns v and 64+v)

    __shared__ float sw1[F_IN * 16];
    __shared__ float sb1[16], ss1[16], so1[16], spw1b[16];
    __shared__ float sfeat[T_PTS * F_IN];
    __shared__ int   smask[T_PTS];
    __shared__ __align__(16) float pw1s[T_PTS * 16];
    __shared__ float sagg1[16];

    // Block-invariant stage-1 params
    for (int i = v; i < F_IN * 16; i += 64) sw1[i] = w1[i];
    if (v < 16) {
        float s = gamma1[v] * rsqrtf(var1[v] + EPSVAL);
        float o = beta1[v] - mean1[v] * s;
        float bb = b1[v];
        ss1[v] = s; so1[v] = o; sb1[v] = bb;
        spw1b[v] = fmaxf(bb, 0.f) * s + o;        // pw1 of a fully-masked point
    }

    // Per-thread stage-2 params
    const float s2v = gamma2[v] * rsqrtf(var2[v] + EPSVAL);
    const float o2v = beta2[v] - mean2[v] * s2v;
    const float b2v = b2[v];
    const float pw2b = fmaxf(b2v, 0.f) * s2v + o2v;  // pw2 of a masked point

    float w2A[16], w2B[16];
#pragma unroll
    for (int j = 0; j < 16; j++) {
        w2A[j] = __ldg(&w2[j * 64 + v]);
        w2B[j] = __ldg(&w2[(16 + j) * 64 + v]);
    }
    BAR64();

    for (int k = bid; k < K_VOX; k += NBLK) {
        // Load this voxel's point features (64 threads, 245 floats)
        for (int i = v; i < T_PTS * F_IN; i += 64)
            sfeat[i] = feat[k * (T_PTS * F_IN) + i];
        BAR64();

        // Mask: point valid iff max over its features != 0
        if (v < T_PTS) {
            float m = sfeat[v * F_IN];
#pragma unroll
            for (int f = 1; f < F_IN; f++) m = fmaxf(m, sfeat[v * F_IN + f]);
            smask[v] = (m != 0.f) ? 1 : 0;
        }
        BAR64();

        // Stage 1: pw1_eff[t][u] (masked rows take the constant pw1b[u])
        for (int e = v; e < T_PTS * 16; e += 64) {
            const int t = e >> 4, u = e & 15;
            float val;
            if (smask[t]) {
                float d = sb1[u];
#pragma unroll
                for (int f = 0; f < F_IN; f++)
                    d = fmaf(sfeat[t * F_IN + f], sw1[f * 16 + u], d);
                val = fmaxf(d, 0.f) * ss1[u] + so1[u];
            } else {
                val = spw1b[u];
            }
            pw1s[e] = val;
        }
        BAR64();

        // agg1[u] = max over ALL t of pw1_eff (reference maxes pre-mask)
        if (v < 16) {
            float m = pw1s[v];
            for (int t = 1; t < T_PTS; t++) m = fmaxf(m, pw1s[t * 16 + v]);
            sagg1[v] = m;
        }
        BAR64();

        // Stage 2: per-channel dot over valid rows
        float aggdot = 0.f;
#pragma unroll
        for (int j = 0; j < 16; j++) aggdot = fmaf(sagg1[j], w2B[j], aggdot);
        const float base2 = b2v + aggdot;

        float vmax = -3.4e38f, amax = -3.4e38f;
        int anyInvalid = 0, anyValid = 0;
        for (int t = 0; t < T_PTS; t++) {
            if (smask[t]) {
                anyValid = 1;
                const float4* row = (const float4*)(pw1s + t * 16);
                float4 r0 = row[0], r1 = row[1], r2 = row[2], r3 = row[3];
                float d0 = base2, d1 = 0.f;
                d0 = fmaf(r0.x, w2A[0], d0);  d1 = fmaf(r0.y, w2A[1], d1);
                d0 = fmaf(r0.z, w2A[2], d0);  d1 = fmaf(r0.w, w2A[3], d1);
                d0 = fmaf(r1.x, w2A[4], d0);  d1 = fmaf(r1.y, w2A[5], d1);
                d0 = fmaf(r1.z, w2A[6], d0);  d1 = fmaf(r1.w, w2A[7], d1);
                d0 = fmaf(r2.x, w2A[8], d0);  d1 = fmaf(r2.y, w2A[9], d1);
                d0 = fmaf(r2.z, w2A[10], d0); d1 = fmaf(r2.w, w2A[11], d1);
                d0 = fmaf(r3.x, w2A[12], d0); d1 = fmaf(r3.y, w2A[13], d1);
                d0 = fmaf(r3.z, w2A[14], d0); d1 = fmaf(r3.w, w2A[15], d1);
                float pw2 = fmaxf(d0 + d1, 0.f) * s2v + o2v;
                vmax = fmaxf(vmax, pw2);
                amax = fmaxf(amax, pw2);
            } else {
                anyInvalid = 1;
            }
        }

        float outA, outB;
        if (!anyValid) {
            outA = 0.f; outB = 0.f;
        } else if (anyInvalid) {
            amax = fmaxf(amax, pw2b);
            outA = fmaxf(vmax, 0.f);
            outB = fmaxf(amax, 0.f);
        } else {
            outA = vmax; outB = amax;
        }

        g_vox[k * C_OUT_DIM + v]      = outA;
        g_vox[k * C_OUT_DIM + 64 + v] = outB;
        BAR64();   // smem reuse next voxel
    }
}

// ---------------------------------------------------------------------------
// Scatter-add staged voxel results into the (now zeroed) grid.
// ---------------------------------------------------------------------------
__global__ __launch_bounds__(256) void scatter_kernel(
    const int* __restrict__ coord,      // [K, 4]
    float*     __restrict__ out)
{
    const int i = blockIdx.x * 256 + threadIdx.x;   // 0 .. K*128-1
    const int k = i >> 7;
    const int c = i & 127;
    const int4 cc = __ldg(&((const int4*)coord)[k]);
    const int base =
        (((cc.x * D_DIM + cc.y) * H_DIM + cc.z) * W_DIM + cc.w) * C_OUT_DIM;
    atomicAdd(out + base + c, g_vox[i]);
}

// ---------------------------------------------------------------------------
extern "C" void kernel_launch(void* const* d_in, const int* in_sizes, int n_in,
                              void* d_out, int out_size) {
    const float* feat   = (const float*)d_in[0];
    const float* w1     = (const float*)d_in[1];
    const float* b1     = (const float*)d_in[2];
    const float* gamma1 = (const float*)d_in[3];
    const float* beta1  = (const float*)d_in[4];
    const float* mean1  = (const float*)d_in[5];
    const float* var1   = (const float*)d_in[6];
    const float* w2     = (const float*)d_in[7];
    const float* b2     = (const float*)d_in[8];
    const float* gamma2 = (const float*)d_in[9];
    const float* beta2  = (const float*)d_in[10];
    const float* var2m  = (const float*)d_in[11];
    const float* var2   = (const float*)d_in[12];
    const int*   coord  = (const int*)d_in[13];
    float* out = (float*)d_out;

    const int n4 = out_size / 4;
    fat_kernel<<<NBLK, 256>>>(feat, w1, b1, gamma1, beta1, mean1, var1,
                              w2, b2, gamma2, beta2, var2m, var2,
                              out, n4);
    scatter_kernel<<<(K_VOX * C_OUT_DIM) / 256, 256>>>(coord, out);
}

// round 4
// speedup vs baseline: 1.0412x; 1.0412x over previous
#include <cuda_runtime.h>

// Problem constants (match reference)
#define K_VOX 12000
#define T_PTS 35
#define F_IN  7
#define D_DIM 10
#define H_DIM 400
#define W_DIM 352
#define C_OUT_DIM 128
#define EPSVAL 1e-3f

// One resident wave: 148 SMs x 4 blocks of 256 threads.
// SM-level role split by residue: residues [0, NC_SM) are compute SMs.
#define NSM     148
#define OCC     4
#define NBLK    (NSM * OCC)            // 592
#define NC_SM   37                     // compute SMs
#define NCBLK   (NC_SM * OCC)          // 148 compute blocks
#define NZBLK   ((NSM - NC_SM) * OCC)  // 444 zero blocks
#define NGROUPS (NCBLK * 4)            // 592 voxel groups
#define ZT      (NZBLK * 256)          // zero threads

// Voxel-wise results staged here (fully overwritten each launch).
__device__ float g_vox[K_VOX * C_OUT_DIM];   // 6.1 MB

#define GBAR(id) asm volatile("bar.sync %0, 64;" :: "r"(id) : "memory")

// ---------------------------------------------------------------------------
// Fat kernel, SM-specialized: blocks whose (bid % 148) < NC_SM run compute
// (4 independent 64-thread voxel groups, ~20 voxels serial each); all other
// blocks stream-zero the 720MB output at the HBM write floor.
// ---------------------------------------------------------------------------
__global__ __launch_bounds__(256, 4) void fat_kernel(
    const float* __restrict__ feat,     // [K, T, F]
    const float* __restrict__ w1,       // [F, 16]
    const float* __restrict__ b1,
    const float* __restrict__ gamma1, const float* __restrict__ beta1,
    const float* __restrict__ mean1,  const float* __restrict__ var1,
    const float* __restrict__ w2,       // [32, 64]
    const float* __restrict__ b2,
    const float* __restrict__ gamma2, const float* __restrict__ beta2,
    const float* __restrict__ mean2,  const float* __restrict__ var2,
    float*       __restrict__ out,      // [1, D, H, W, 128] — zeroed here
    int n4)                             // out_size / 4
{
    const int bid = blockIdx.x;
    const int tid = threadIdx.x;
    const int res = bid % NSM;

    if (res >= NC_SM) {
        // ---------------- Zero role (dedicated SMs) ----------------
        const int zb  = (bid / NSM) * (NSM - NC_SM) + (res - NC_SM);
        const int zid = zb * 256 + tid;
        float4* o4 = (float4*)out;
        const float4 z = make_float4(0.f, 0.f, 0.f, 0.f);
        for (int i = zid; i < n4; i += ZT) o4[i] = z;
        return;
    }

    // ---------------- Compute role (dedicated SMs) ----------------
    const int cb = (bid / NSM) * NC_SM + res;   // compute block 0..147
    const int g  = tid >> 6;                    // group 0..3
    const int v  = tid & 63;                    // channel within group
    const int gidx = cb * 4 + g;                // group id 0..591

    __shared__ float sw1[F_IN * 16];
    __shared__ float sb1[16], ss1[16], so1[16], spw1b[16];
    __shared__ float sfeat[4][T_PTS * F_IN];
    __shared__ int   smask[4][T_PTS];
    __shared__ __align__(16) float pw1s[4][T_PTS * 16];
    __shared__ float sagg1[4][16];

    // Block-invariant stage-1 params
    if (tid < F_IN * 16) sw1[tid] = w1[tid];
    if (tid < 16) {
        float s = gamma1[tid] * rsqrtf(var1[tid] + EPSVAL);
        float o = beta1[tid] - mean1[tid] * s;
        float bb = b1[tid];
        ss1[tid] = s; so1[tid] = o; sb1[tid] = bb;
        spw1b[tid] = fmaxf(bb, 0.f) * s + o;     // pw1 of a fully-masked point
    }

    // Per-thread stage-2 params (thread owns channels v and 64+v)
    const float s2v = gamma2[v] * rsqrtf(var2[v] + EPSVAL);
    const float o2v = beta2[v] - mean2[v] * s2v;
    const float b2v = b2[v];
    const float pw2b = fmaxf(b2v, 0.f) * s2v + o2v;   // pw2 of a masked point

    float w2A[16], w2B[16];
#pragma unroll
    for (int j = 0; j < 16; j++) {
        w2A[j] = __ldg(&w2[j * 64 + v]);
        w2B[j] = __ldg(&w2[(16 + j) * 64 + v]);
    }
    __syncthreads();   // params visible to all groups

    const int barid = g + 1;   // named barrier per 64-thread group

    for (int k = gidx; k < K_VOX; k += NGROUPS) {
        // Load this voxel's point features
        for (int i = v; i < T_PTS * F_IN; i += 64)
            sfeat[g][i] = feat[k * (T_PTS * F_IN) + i];
        GBAR(barid);

        // Mask: point valid iff max over its features != 0
        if (v < T_PTS) {
            float m = sfeat[g][v * F_IN];
#pragma unroll
            for (int f = 1; f < F_IN; f++) m = fmaxf(m, sfeat[g][v * F_IN + f]);
            smask[g][v] = (m != 0.f) ? 1 : 0;
        }
        GBAR(barid);

        // Stage 1: pw1_eff[t][u] (masked rows take the constant pw1b[u])
        for (int e = v; e < T_PTS * 16; e += 64) {
            const int t = e >> 4, u = e & 15;
            float val;
            if (smask[g][t]) {
                float d = sb1[u];
#pragma unroll
                for (int f = 0; f < F_IN; f++)
                    d = fmaf(sfeat[g][t * F_IN + f], sw1[f * 16 + u], d);
                val = fmaxf(d, 0.f) * ss1[u] + so1[u];
            } else {
                val = spw1b[u];
            }
            pw1s[g][e] = val;
        }
        GBAR(barid);

        // agg1[u] = max over ALL t of pw1_eff (reference maxes pre-mask)
        if (v < 16) {
            float m = pw1s[g][v];
            for (int t = 1; t < T_PTS; t++) m = fmaxf(m, pw1s[g][t * 16 + v]);
            sagg1[g][v] = m;
        }
        GBAR(barid);

        // Stage 2: per-channel dot over valid rows
        float aggdot = 0.f;
#pragma unroll
        for (int j = 0; j < 16; j++) aggdot = fmaf(sagg1[g][j], w2B[j], aggdot);
        const float base2 = b2v + aggdot;

        float vmax = -3.4e38f, amax = -3.4e38f;
        int anyInvalid = 0, anyValid = 0;
        for (int t = 0; t < T_PTS; t++) {
            if (smask[g][t]) {
                anyValid = 1;
                const float4* row = (const float4*)(pw1s[g] + t * 16);
                float4 r0 = row[0], r1 = row[1], r2 = row[2], r3 = row[3];
                float d0 = base2, d1 = 0.f;
                d0 = fmaf(r0.x, w2A[0], d0);  d1 = fmaf(r0.y, w2A[1], d1);
                d0 = fmaf(r0.z, w2A[2], d0);  d1 = fmaf(r0.w, w2A[3], d1);
                d0 = fmaf(r1.x, w2A[4], d0);  d1 = fmaf(r1.y, w2A[5], d1);
                d0 = fmaf(r1.z, w2A[6], d0);  d1 = fmaf(r1.w, w2A[7], d1);
                d0 = fmaf(r2.x, w2A[8], d0);  d1 = fmaf(r2.y, w2A[9], d1);
                d0 = fmaf(r2.z, w2A[10], d0); d1 = fmaf(r2.w, w2A[11], d1);
                d0 = fmaf(r3.x, w2A[12], d0); d1 = fmaf(r3.y, w2A[13], d1);
                d0 = fmaf(r3.z, w2A[14], d0); d1 = fmaf(r3.w, w2A[15], d1);
                float pw2 = fmaxf(d0 + d1, 0.f) * s2v + o2v;
                vmax = fmaxf(vmax, pw2);
                amax = fmaxf(amax, pw2);
            } else {
                anyInvalid = 1;
            }
        }

        float outA, outB;
        if (!anyValid) {
            outA = 0.f; outB = 0.f;
        } else if (anyInvalid) {
            amax = fmaxf(amax, pw2b);
            outA = fmaxf(vmax, 0.f);
            outB = fmaxf(amax, 0.f);
        } else {
            outA = vmax; outB = amax;
        }

        g_vox[k * C_OUT_DIM + v]      = outA;
        g_vox[k * C_OUT_DIM + 64 + v] = outB;
        GBAR(barid);   // smem reuse next voxel
    }
}

// ---------------------------------------------------------------------------
// Scatter-add staged voxel results into the (now zeroed) grid.
// ---------------------------------------------------------------------------
__global__ __launch_bounds__(256) void scatter_kernel(
    const int* __restrict__ coord,      // [K, 4]
    float*     __restrict__ out)
{
    const int i = blockIdx.x * 256 + threadIdx.x;   // 0 .. K*128-1
    const int k = i >> 7;
    const int c = i & 127;
    const int4 cc = __ldg(&((const int4*)coord)[k]);
    const int base =
        (((cc.x * D_DIM + cc.y) * H_DIM + cc.z) * W_DIM + cc.w) * C_OUT_DIM;
    atomicAdd(out + base + c, g_vox[i]);
}

// ---------------------------------------------------------------------------
extern "C" void kernel_launch(void* const* d_in, const int* in_sizes, int n_in,
                              void* d_out, int out_size) {
    const float* feat   = (const float*)d_in[0];
    const float* w1     = (const float*)d_in[1];
    const float* b1     = (const float*)d_in[2];
    const float* gamma1 = (const float*)d_in[3];
    const float* beta1  = (const float*)d_in[4];
    const float* mean1  = (const float*)d_in[5];
    const float* var1   = (const float*)d_in[6];
    const float* w2     = (const float*)d_in[7];
    const float* b2     = (const float*)d_in[8];
    const float* gamma2 = (const float*)d_in[9];
    const float* beta2  = (const float*)d_in[10];
    const float* mean2  = (const float*)d_in[11];
    const float* var2   = (const float*)d_in[12];
    const int*   coord  = (const int*)d_in[13];
    float* out = (float*)d_out;

    const int n4 = out_size / 4;
    fat_kernel<<<NBLK, 256>>>(feat, w1, b1, gamma1, beta1, mean1, var1,
                              w2, b2, gamma2, beta2, mean2, var2,
                              out, n4);
    scatter_kernel<<<(K_VOX * C_OUT_DIM) / 256, 256>>>(coord, out);
}